// round 1
// baseline (speedup 1.0000x reference)
#include <cuda_runtime.h>
#include <math.h>

// Output[b] = W_cls * prod_q cos^2( (tanh(x_b . w_q + b_q) - tanh(ref_q)) / 2 ) + b_cls
// (product-state overlap factorizes per qubit; overlap is real)

#define THREADS 512
#define WARPS_PER_BLOCK (THREADS / 32)
#define D 1024
#define DV (D / 4)          // 256 float4 per row
#define CHUNKS (DV / 32)    // 8 float4 per lane

__global__ __launch_bounds__(THREADS, 2)
void qkc_kernel(const float* __restrict__ features,  // [B, 1024]
                const float* __restrict__ W_proj,    // [4, 1024]
                const float* __restrict__ b_proj,    // [4]
                const float* __restrict__ ref_vec,   // [4]
                const float* __restrict__ W_cls,     // [1,1]
                const float* __restrict__ b_cls,     // [1]
                float* __restrict__ out,             // [B]
                int B)
{
    __shared__ float4 ws[4][DV];   // 16 KB

    // Cooperative load of W_proj into shared (as float4)
    const float4* Wv = reinterpret_cast<const float4*>(W_proj);
    #pragma unroll
    for (int i = threadIdx.x; i < 4 * DV; i += THREADS) {
        ws[i >> 8][i & (DV - 1)] = Wv[i];
    }
    __syncthreads();

    const int warp = threadIdx.x >> 5;
    const int lane = threadIdx.x & 31;
    const int row  = blockIdx.x * WARPS_PER_BLOCK + warp;
    if (row >= B) return;

    const float4* __restrict__ x =
        reinterpret_cast<const float4*>(features + (size_t)row * D);

    float a0 = 0.f, a1 = 0.f, a2 = 0.f, a3 = 0.f;

    // Stage all 8 global loads first for max MLP, then consume.
    float4 xv[CHUNKS];
    #pragma unroll
    for (int c = 0; c < CHUNKS; ++c) {
        xv[c] = __ldcs(&x[lane + 32 * c]);   // streaming: no reuse, spare L2
    }

    #pragma unroll
    for (int c = 0; c < CHUNKS; ++c) {
        const int p = lane + 32 * c;
        float4 w0 = ws[0][p];
        float4 w1 = ws[1][p];
        float4 w2 = ws[2][p];
        float4 w3 = ws[3][p];
        a0 += xv[c].x * w0.x + xv[c].y * w0.y + xv[c].z * w0.z + xv[c].w * w0.w;
        a1 += xv[c].x * w1.x + xv[c].y * w1.y + xv[c].z * w1.z + xv[c].w * w1.w;
        a2 += xv[c].x * w2.x + xv[c].y * w2.y + xv[c].z * w2.z + xv[c].w * w2.w;
        a3 += xv[c].x * w3.x + xv[c].y * w3.y + xv[c].z * w3.z + xv[c].w * w3.w;
    }

    // Warp reduction of the 4 dot products
    #pragma unroll
    for (int o = 16; o > 0; o >>= 1) {
        a0 += __shfl_xor_sync(0xFFFFFFFFu, a0, o);
        a1 += __shfl_xor_sync(0xFFFFFFFFu, a1, o);
        a2 += __shfl_xor_sync(0xFFFFFFFFu, a2, o);
        a3 += __shfl_xor_sync(0xFFFFFFFFu, a3, o);
    }

    if (lane == 0) {
        float acc[4] = {a0, a1, a2, a3};
        float fid = 1.0f;
        #pragma unroll
        for (int q = 0; q < 4; ++q) {
            float t = tanhf(acc[q] + b_proj[q]);
            float r = tanhf(ref_vec[q]);
            float cd = cosf((t - r) * 0.5f);
            fid *= cd * cd;
        }
        out[row] = fid * W_cls[0] + b_cls[0];
    }
}

extern "C" void kernel_launch(void* const* d_in, const int* in_sizes, int n_in,
                              void* d_out, int out_size)
{
    const float* features = (const float*)d_in[0];
    const float* W_proj   = (const float*)d_in[1];
    const float* b_proj   = (const float*)d_in[2];
    const float* ref_vec  = (const float*)d_in[3];
    const float* W_cls    = (const float*)d_in[4];
    const float* b_cls    = (const float*)d_in[5];
    float* out = (float*)d_out;

    const int B = in_sizes[0] / D;   // 65536
    const int rows_per_block = WARPS_PER_BLOCK;
    const int grid = (B + rows_per_block - 1) / rows_per_block;

    qkc_kernel<<<grid, THREADS>>>(features, W_proj, b_proj, ref_vec,
                                  W_cls, b_cls, out, B);
}

// round 2
// speedup vs baseline: 1.2905x; 1.2905x over previous
#include <cuda_runtime.h>
#include <math.h>

// out[b] = W_cls * prod_q cos^2( (tanh(x_b . w_q + b_q) - tanh(ref_q)) / 2 ) + b_cls
// Product-state overlap factorizes per qubit; overlap is real.
//
// R2: 4 rows per warp so each shared-memory W read is amortized over 4 rows
// (R1 was LDS-bound: 16KB smem traffic per 4KB of HBM traffic).

#define THREADS 256
#define WARPS_PER_BLOCK (THREADS / 32)
#define D 1024
#define DV (D / 4)          // 256 float4 per row
#define CHUNKS (DV / 32)    // 8 float4 slots per lane
#define ROWS 4              // rows per warp

__global__ __launch_bounds__(THREADS)
void qkc_kernel(const float* __restrict__ features,  // [B, 1024]
                const float* __restrict__ W_proj,    // [4, 1024]
                const float* __restrict__ b_proj,    // [4]
                const float* __restrict__ ref_vec,   // [4]
                const float* __restrict__ W_cls,     // [1,1]
                const float* __restrict__ b_cls,     // [1]
                float* __restrict__ out,             // [B]
                int B)
{
    __shared__ float4 ws[4][DV];   // 16 KB

    const float4* Wv = reinterpret_cast<const float4*>(W_proj);
    #pragma unroll
    for (int i = threadIdx.x; i < 4 * DV; i += THREADS) {
        ws[i >> 8][i & (DV - 1)] = Wv[i];
    }
    __syncthreads();

    const int warp = threadIdx.x >> 5;
    const int lane = threadIdx.x & 31;
    const int row0 = (blockIdx.x * WARPS_PER_BLOCK + warp) * ROWS;
    if (row0 >= B) return;

    const float4* __restrict__ xbase = reinterpret_cast<const float4*>(features);

    float acc[ROWS][4];
    #pragma unroll
    for (int r = 0; r < ROWS; ++r)
        #pragma unroll
        for (int q = 0; q < 4; ++q)
            acc[r][q] = 0.f;

    #pragma unroll
    for (int c = 0; c < CHUNKS; ++c) {
        const int p = lane + 32 * c;

        // 4 independent global loads (one per row) -> MLP=4 per chunk,
        // chunks fully unrolled so ptxas front-batches more.
        float4 xr[ROWS];
        #pragma unroll
        for (int r = 0; r < ROWS; ++r)
            xr[r] = __ldcs(&xbase[(size_t)(row0 + r) * DV + p]);

        #pragma unroll
        for (int q = 0; q < 4; ++q) {
            float4 w = ws[q][p];   // one LDS.128 serves 4 rows
            #pragma unroll
            for (int r = 0; r < ROWS; ++r) {
                acc[r][q] += xr[r].x * w.x + xr[r].y * w.y
                           + xr[r].z * w.z + xr[r].w * w.w;
            }
        }
    }

    // Butterfly reduce all 16 accumulators across the warp.
    #pragma unroll
    for (int r = 0; r < ROWS; ++r)
        #pragma unroll
        for (int q = 0; q < 4; ++q)
            #pragma unroll
            for (int o = 16; o > 0; o >>= 1)
                acc[r][q] += __shfl_xor_sync(0xFFFFFFFFu, acc[r][q], o);

    // Lanes 0..3 each finish one row (all lanes hold all sums after butterfly).
    if (lane < ROWS) {
        float s[4];
        #pragma unroll
        for (int q = 0; q < 4; ++q) {
            float v = acc[0][q];
            if (lane == 1) v = acc[1][q];
            if (lane == 2) v = acc[2][q];
            if (lane == 3) v = acc[3][q];
            s[q] = v;
        }
        float fid = 1.0f;
        #pragma unroll
        for (int q = 0; q < 4; ++q) {
            float t  = tanhf(s[q] + b_proj[q]);
            float rr = tanhf(ref_vec[q]);
            float cd = cosf((t - rr) * 0.5f);
            fid *= cd * cd;
        }
        out[row0 + lane] = fid * W_cls[0] + b_cls[0];
    }
}

extern "C" void kernel_launch(void* const* d_in, const int* in_sizes, int n_in,
                              void* d_out, int out_size)
{
    const float* features = (const float*)d_in[0];
    const float* W_proj   = (const float*)d_in[1];
    const float* b_proj   = (const float*)d_in[2];
    const float* ref_vec  = (const float*)d_in[3];
    const float* W_cls    = (const float*)d_in[4];
    const float* b_cls    = (const float*)d_in[5];
    float* out = (float*)d_out;

    const int B = in_sizes[0] / D;                    // 65536
    const int rows_per_block = WARPS_PER_BLOCK * ROWS; // 32
    const int grid = (B + rows_per_block - 1) / rows_per_block;

    qkc_kernel<<<grid, THREADS>>>(features, W_proj, b_proj, ref_vec,
                                  W_cls, b_cls, out, B);
}

// round 3
// speedup vs baseline: 1.2938x; 1.0026x over previous
#include <cuda_runtime.h>
#include <math.h>

// out[b] = W_cls * prod_q cos^2( (tanh(x_b . w_q + b_q) - tanh(ref_q)) / 2 ) + b_cls
// Product-state overlap factorizes per qubit; overlap is real.
//
// R3: force 4 CTAs/SM (reg cap 64) to raise resident warps 24->32; R2 was
// latency-bound (DRAM 68.7%, issue 36%, occ 33% @ 73 regs).

#define THREADS 256
#define WARPS_PER_BLOCK (THREADS / 32)
#define D 1024
#define DV (D / 4)          // 256 float4 per row
#define CHUNKS (DV / 32)    // 8 float4 slots per lane
#define ROWS 4              // rows per warp

__global__ __launch_bounds__(THREADS, 4)
void qkc_kernel(const float* __restrict__ features,  // [B, 1024]
                const float* __restrict__ W_proj,    // [4, 1024]
                const float* __restrict__ b_proj,    // [4]
                const float* __restrict__ ref_vec,   // [4]
                const float* __restrict__ W_cls,     // [1,1]
                const float* __restrict__ b_cls,     // [1]
                float* __restrict__ out,             // [B]
                int B)
{
    __shared__ float4 ws[4][DV];   // 16 KB

    const float4* Wv = reinterpret_cast<const float4*>(W_proj);
    #pragma unroll
    for (int i = threadIdx.x; i < 4 * DV; i += THREADS) {
        ws[i >> 8][i & (DV - 1)] = Wv[i];
    }
    __syncthreads();

    const int warp = threadIdx.x >> 5;
    const int lane = threadIdx.x & 31;
    const int row0 = (blockIdx.x * WARPS_PER_BLOCK + warp) * ROWS;
    if (row0 >= B) return;

    // Single base pointer; per-row offsets are compile-time multiples of DV.
    const float4* __restrict__ x0 =
        reinterpret_cast<const float4*>(features) + (size_t)row0 * DV + lane;

    float acc[ROWS][4];
    #pragma unroll
    for (int r = 0; r < ROWS; ++r)
        #pragma unroll
        for (int q = 0; q < 4; ++q)
            acc[r][q] = 0.f;

    #pragma unroll
    for (int c = 0; c < CHUNKS; ++c) {
        const int p = lane + 32 * c;

        // 4 independent streaming loads (one per row).
        float4 xr[ROWS];
        #pragma unroll
        for (int r = 0; r < ROWS; ++r)
            xr[r] = __ldcs(x0 + r * DV + 32 * c);

        #pragma unroll
        for (int q = 0; q < 4; ++q) {
            float4 w = ws[q][p];   // one LDS.128 serves 4 rows
            #pragma unroll
            for (int r = 0; r < ROWS; ++r) {
                acc[r][q] += xr[r].x * w.x + xr[r].y * w.y
                           + xr[r].z * w.z + xr[r].w * w.w;
            }
        }
    }

    // Butterfly reduce all 16 accumulators across the warp.
    #pragma unroll
    for (int r = 0; r < ROWS; ++r)
        #pragma unroll
        for (int q = 0; q < 4; ++q)
            #pragma unroll
            for (int o = 16; o > 0; o >>= 1)
                acc[r][q] += __shfl_xor_sync(0xFFFFFFFFu, acc[r][q], o);

    // Lanes 0..3 each finish one row (all lanes hold the full sums).
    if (lane < ROWS) {
        float fid = 1.0f;
        #pragma unroll
        for (int q = 0; q < 4; ++q) {
            // lane r needs acc[r][q]; select without divergent if-chain.
            float v = (lane == 0) ? acc[0][q]
                    : (lane == 1) ? acc[1][q]
                    : (lane == 2) ? acc[2][q]
                    :               acc[3][q];
            float t  = tanhf(v + b_proj[q]);
            float rr = tanhf(ref_vec[q]);
            float cd = cosf((t - rr) * 0.5f);
            fid *= cd * cd;
        }
        out[row0 + lane] = fid * W_cls[0] + b_cls[0];
    }
}

extern "C" void kernel_launch(void* const* d_in, const int* in_sizes, int n_in,
                              void* d_out, int out_size)
{
    const float* features = (const float*)d_in[0];
    const float* W_proj   = (const float*)d_in[1];
    const float* b_proj   = (const float*)d_in[2];
    const float* ref_vec  = (const float*)d_in[3];
    const float* W_cls    = (const float*)d_in[4];
    const float* b_cls    = (const float*)d_in[5];
    float* out = (float*)d_out;

    const int B = in_sizes[0] / D;                     // 65536
    const int rows_per_block = WARPS_PER_BLOCK * ROWS; // 32
    const int grid = (B + rows_per_block - 1) / rows_per_block;

    qkc_kernel<<<grid, THREADS>>>(features, W_proj, b_proj, ref_vec,
                                  W_cls, b_cls, out, B);
}

// round 4
// speedup vs baseline: 1.3495x; 1.0430x over previous
#include <cuda_runtime.h>
#include <math.h>
#include <stdint.h>

// out[b] = W_cls * prod_q cos^2( (tanh(x_b . w_q + b_q) - tanh(ref_q)) / 2 ) + b_cls
//
// R4: cp.async smem staging (in-flight bytes live in SMEM, not the RF),
// persistent CTAs (one W prologue), cross-block pipelined prefetch.

#define THREADS 256
#define WARPS   8
#define D       1024
#define DV      256          // float4 per row
#define CHUNKS  8            // 8 chunks of 32 float4 per row
#define ROWS    4            // rows per warp
#define RPB     (WARPS * ROWS)   // 32 rows per CTA block-iter

__device__ __forceinline__ void cp_async16(uint32_t dst_smem, const void* src) {
    asm volatile("cp.async.cg.shared.global [%0], [%1], 16;\n"
                 :: "r"(dst_smem), "l"(src) : "memory");
}
__device__ __forceinline__ void cp_commit() {
    asm volatile("cp.async.commit_group;\n" ::: "memory");
}
template <int N>
__device__ __forceinline__ void cp_wait() {
    asm volatile("cp.async.wait_group %0;\n" :: "n"(N) : "memory");
}

__global__ __launch_bounds__(THREADS, 4)
void qkc_kernel(const float* __restrict__ features,  // [B, 1024]
                const float* __restrict__ W_proj,    // [4, 1024]
                const float* __restrict__ b_proj,    // [4]
                const float* __restrict__ ref_vec,   // [4]
                const float* __restrict__ W_cls,     // [1,1]
                const float* __restrict__ b_cls,     // [1]
                float* __restrict__ out,             // [B]
                int B)
{
    __shared__ float4 ws[4][DV];                     // 16 KB
    __shared__ float4 stage[WARPS][2][ROWS][32];     // 32 KB (2KB/warp/stage)

    // One-time W prologue (persistent CTA => amortized over all blocks)
    const float4* Wv = reinterpret_cast<const float4*>(W_proj);
    #pragma unroll
    for (int i = threadIdx.x; i < 4 * DV; i += THREADS)
        ws[i >> 8][i & (DV - 1)] = Wv[i];
    __syncthreads();

    const int warp = threadIdx.x >> 5;
    const int lane = threadIdx.x & 31;
    const int NB = B / RPB;               // row-blocks total
    const int stride = gridDim.x;

    const float4* __restrict__ xbase = reinterpret_cast<const float4*>(features);

    // smem addresses of this warp's two stage buffers (per row)
    uint32_t sbuf[2][ROWS];
    #pragma unroll
    for (int s = 0; s < 2; ++s)
        #pragma unroll
        for (int r = 0; r < ROWS; ++r)
            sbuf[s][r] = (uint32_t)__cvta_generic_to_shared(&stage[warp][s][r][lane]);

    int rb = blockIdx.x;
    if (rb >= NB) return;

    // pointer to this warp's 4 rows within block rb, at this lane
    const float4* ptr_cur = xbase + (size_t)(rb * RPB + warp * ROWS) * DV + lane;

    // Prime the pipe: chunks 0 and 1 of the first block
    #pragma unroll
    for (int r = 0; r < ROWS; ++r) cp_async16(sbuf[0][r], ptr_cur + (size_t)r * DV);
    cp_commit();
    #pragma unroll
    for (int r = 0; r < ROWS; ++r) cp_async16(sbuf[1][r], ptr_cur + (size_t)r * DV + 32);
    cp_commit();

    for (; rb < NB; rb += stride) {
        const int rb_next = (rb + stride < NB) ? (rb + stride) : 0;  // dummy prefetch at tail
        const float4* ptr_next =
            xbase + (size_t)(rb_next * RPB + warp * ROWS) * DV + lane;

        float acc[ROWS][4];
        #pragma unroll
        for (int r = 0; r < ROWS; ++r)
            #pragma unroll
            for (int q = 0; q < 4; ++q)
                acc[r][q] = 0.f;

        #pragma unroll
        for (int c = 0; c < CHUNKS; ++c) {
            cp_wait<1>();   // chunk c's group is complete (FIFO, <=1 pending)

            // consume chunk c from its stage buffer
            float4 xr[ROWS];
            #pragma unroll
            for (int r = 0; r < ROWS; ++r)
                xr[r] = stage[warp][c & 1][r][lane];

            const int p = lane + 32 * c;
            #pragma unroll
            for (int q = 0; q < 4; ++q) {
                float4 w = ws[q][p];
                #pragma unroll
                for (int r = 0; r < ROWS; ++r)
                    acc[r][q] += xr[r].x * w.x + xr[r].y * w.y
                               + xr[r].z * w.z + xr[r].w * w.w;
            }

            // issue chunk c+2 of the stream (wraps into next block's chunks 0,1)
            const float4* ip = (c < CHUNKS - 2) ? ptr_cur : ptr_next;
            const int     ic = (c < CHUNKS - 2) ? (c + 2)  : (c - (CHUNKS - 2));
            #pragma unroll
            for (int r = 0; r < ROWS; ++r)
                cp_async16(sbuf[c & 1][r], ip + (size_t)r * DV + 32 * ic);
            cp_commit();
        }

        // Butterfly reduce (overlaps with the 2 prefetched groups in flight)
        #pragma unroll
        for (int r = 0; r < ROWS; ++r)
            #pragma unroll
            for (int q = 0; q < 4; ++q)
                #pragma unroll
                for (int o = 16; o > 0; o >>= 1)
                    acc[r][q] += __shfl_xor_sync(0xFFFFFFFFu, acc[r][q], o);

        if (lane < ROWS) {
            float fid = 1.0f;
            #pragma unroll
            for (int q = 0; q < 4; ++q) {
                float v = (lane == 0) ? acc[0][q]
                        : (lane == 1) ? acc[1][q]
                        : (lane == 2) ? acc[2][q]
                        :               acc[3][q];
                float t  = tanhf(v + b_proj[q]);
                float rr = tanhf(ref_vec[q]);
                float cd = cosf((t - rr) * 0.5f);
                fid *= cd * cd;
            }
            out[rb * RPB + warp * ROWS + lane] = fid * W_cls[0] + b_cls[0];
        }

        ptr_cur = ptr_next;
    }

    cp_wait<0>();  // drain dummy prefetches before exit
}

extern "C" void kernel_launch(void* const* d_in, const int* in_sizes, int n_in,
                              void* d_out, int out_size)
{
    const float* features = (const float*)d_in[0];
    const float* W_proj   = (const float*)d_in[1];
    const float* b_proj   = (const float*)d_in[2];
    const float* ref_vec  = (const float*)d_in[3];
    const float* W_cls    = (const float*)d_in[4];
    const float* b_cls    = (const float*)d_in[5];
    float* out = (float*)d_out;

    const int B = in_sizes[0] / D;     // 65536
    const int NB = B / RPB;            // 2048 row-blocks

    static int sms = 0;
    if (sms == 0) cudaDeviceGetAttribute(&sms, cudaDevAttrMultiProcessorCount, 0);
    int grid = sms * 4;                // persistent: 4 CTAs per SM
    if (grid > NB) grid = NB;

    qkc_kernel<<<grid, THREADS>>>(features, W_proj, b_proj, ref_vec,
                                  W_cls, b_cls, out, B);
}

// round 6
// speedup vs baseline: 1.3504x; 1.0007x over previous
#include <cuda_runtime.h>
#include <math.h>
#include <stdint.h>

// out[b] = W_cls * prod_q cos^2( (tanh(x_b . w_q + b_q) - tanh(ref_q)) / 2 ) + b_cls
// Product-state overlap factorizes per qubit; overlap is real.
//
// R6: R4 (cp.async smem staging, persistent CTAs, cross-block pipeline,
// PROVEN full-butterfly reduction) + empty-commit wrap fix (no redundant
// prefetch reads on each CTA's final iteration).

#define THREADS 256
#define WARPS   8
#define D       1024
#define DV      256
#define CHUNKS  8
#define ROWS    4
#define RPB     (WARPS * ROWS)   // 32 rows per block-iter

__device__ __forceinline__ void cp_async16(uint32_t dst_smem, const void* src) {
    asm volatile("cp.async.cg.shared.global [%0], [%1], 16;\n"
                 :: "r"(dst_smem), "l"(src) : "memory");
}
__device__ __forceinline__ void cp_commit() {
    asm volatile("cp.async.commit_group;\n" ::: "memory");
}
template <int N>
__device__ __forceinline__ void cp_wait() {
    asm volatile("cp.async.wait_group %0;\n" :: "n"(N) : "memory");
}

__global__ __launch_bounds__(THREADS, 4)
void qkc_kernel(const float* __restrict__ features,
                const float* __restrict__ W_proj,
                const float* __restrict__ b_proj,
                const float* __restrict__ ref_vec,
                const float* __restrict__ W_cls,
                const float* __restrict__ b_cls,
                float* __restrict__ out,
                int B)
{
    __shared__ float4 ws[4][DV];                     // 16 KB
    __shared__ float4 stage[WARPS][2][ROWS][32];     // 32 KB

    const float4* Wv = reinterpret_cast<const float4*>(W_proj);
    #pragma unroll
    for (int i = threadIdx.x; i < 4 * DV; i += THREADS)
        ws[i >> 8][i & (DV - 1)] = Wv[i];
    __syncthreads();

    const int warp = threadIdx.x >> 5;
    const int lane = threadIdx.x & 31;
    const int NB = B / RPB;
    const int stride = gridDim.x;

    const float4* __restrict__ xbase = reinterpret_cast<const float4*>(features);

    uint32_t sbuf[2][ROWS];
    #pragma unroll
    for (int s = 0; s < 2; ++s)
        #pragma unroll
        for (int r = 0; r < ROWS; ++r)
            sbuf[s][r] = (uint32_t)__cvta_generic_to_shared(&stage[warp][s][r][lane]);

    int rb = blockIdx.x;
    if (rb >= NB) return;

    const float4* ptr_cur = xbase + (size_t)(rb * RPB + warp * ROWS) * DV + lane;

    // Prime the pipe: chunks 0,1 of the first block
    #pragma unroll
    for (int r = 0; r < ROWS; ++r) cp_async16(sbuf[0][r], ptr_cur + (size_t)r * DV);
    cp_commit();
    #pragma unroll
    for (int r = 0; r < ROWS; ++r) cp_async16(sbuf[1][r], ptr_cur + (size_t)r * DV + 32);
    cp_commit();

    for (; rb < NB; rb += stride) {
        const bool has_next = (rb + stride < NB);
        const float4* ptr_next =
            xbase + (size_t)((size_t)(rb + stride) * RPB + warp * ROWS) * DV + lane;

        float acc[ROWS][4];
        #pragma unroll
        for (int r = 0; r < ROWS; ++r)
            #pragma unroll
            for (int q = 0; q < 4; ++q)
                acc[r][q] = 0.f;

        #pragma unroll
        for (int c = 0; c < CHUNKS; ++c) {
            cp_wait<1>();   // chunk c's group complete (FIFO, <=1 younger pending)

            float4 xr[ROWS];
            #pragma unroll
            for (int r = 0; r < ROWS; ++r)
                xr[r] = stage[warp][c & 1][r][lane];

            const int p = lane + 32 * c;
            #pragma unroll
            for (int q = 0; q < 4; ++q) {
                float4 w = ws[q][p];
                #pragma unroll
                for (int r = 0; r < ROWS; ++r)
                    acc[r][q] += xr[r].x * w.x + xr[r].y * w.y
                               + xr[r].z * w.z + xr[r].w * w.w;
            }

            // Issue chunk c+2 of the stream. On the final iteration the two
            // wrap groups are EMPTY commits: no redundant reads, FIFO intact
            // (an empty group completes immediately).
            if (c < CHUNKS - 2) {
                #pragma unroll
                for (int r = 0; r < ROWS; ++r)
                    cp_async16(sbuf[c & 1][r], ptr_cur + (size_t)r * DV + 32 * (c + 2));
            } else if (has_next) {
                #pragma unroll
                for (int r = 0; r < ROWS; ++r)
                    cp_async16(sbuf[c & 1][r],
                               ptr_next + (size_t)r * DV + 32 * (c - (CHUNKS - 2)));
            }
            cp_commit();
        }

        // Full butterfly reduction (proven in R2-R4). Overlaps with the
        // two in-flight prefetch groups of the next block.
        #pragma unroll
        for (int r = 0; r < ROWS; ++r)
            #pragma unroll
            for (int q = 0; q < 4; ++q)
                #pragma unroll
                for (int o = 16; o > 0; o >>= 1)
                    acc[r][q] += __shfl_xor_sync(0xFFFFFFFFu, acc[r][q], o);

        if (lane < ROWS) {
            float fid = 1.0f;
            #pragma unroll
            for (int q = 0; q < 4; ++q) {
                float v = (lane == 0) ? acc[0][q]
                        : (lane == 1) ? acc[1][q]
                        : (lane == 2) ? acc[2][q]
                        :               acc[3][q];
                float t  = tanhf(v + b_proj[q]);
                float rr = tanhf(ref_vec[q]);
                float cd = cosf((t - rr) * 0.5f);
                fid *= cd * cd;
            }
            out[rb * RPB + warp * ROWS + lane] = fid * W_cls[0] + b_cls[0];
        }

        ptr_cur = ptr_next;
    }

    cp_wait<0>();   // drain (empty) groups before exit
}

extern "C" void kernel_launch(void* const* d_in, const int* in_sizes, int n_in,
                              void* d_out, int out_size)
{
    const float* features = (const float*)d_in[0];
    const float* W_proj   = (const float*)d_in[1];
    const float* b_proj   = (const float*)d_in[2];
    const float* ref_vec  = (const float*)d_in[3];
    const float* W_cls    = (const float*)d_in[4];
    const float* b_cls    = (const float*)d_in[5];
    float* out = (float*)d_out;

    const int B  = in_sizes[0] / D;   // 65536
    const int NB = B / RPB;           // 2048

    static int sms = 0;
    if (sms == 0) cudaDeviceGetAttribute(&sms, cudaDevAttrMultiProcessorCount, 0);
    int grid = sms * 4;
    if (grid > NB) grid = NB;

    qkc_kernel<<<grid, THREADS>>>(features, W_proj, b_proj, ref_vec,
                                  W_cls, b_cls, out, B);
}